// round 1
// baseline (speedup 1.0000x reference)
#include <cuda_runtime.h>
#include <math.h>

// Problem constants
#define Nn   131072
#define Ee   1048576
#define Bb   1024
#define FIN  128
#define HID  128
#define DD   384      // 3*HID concat
#define KK   30       // sort-pool k
#define C1n  16
#define C2n  32
#define KERNL 5
#define L2n  26       // KK - KERNL + 1
#define PL   13       // pooled length
#define FLAT 416      // C2n * PL
#define EPSc 1e-5f
#define SMAX 2048     // max nodes per graph we handle (mean is 128)

// ---------------- scratch (device globals; no runtime allocation) ----------
__device__ float g_dis[Nn];                       // rsqrt(deg), deg accumulated here first
__device__ float g_Agg[(size_t)Nn * HID];         // aggregation buffer
__device__ float g_X[(size_t)Nn * DD];            // concatenated layer outputs
__device__ int   g_counts[Bb];
__device__ int   g_starts[Bb];

// ---------------- init: dis accumulator = 1 (self loop), counts = 0 --------
__global__ void init_misc_kernel() {
    int i = blockIdx.x * blockDim.x + threadIdx.x;
    if (i < Nn) g_dis[i] = 1.0f;
    if (i < Bb) g_counts[i] = 0;
}

// ---------------- degree over col --------------------------------------------
__global__ void deg_edges_kernel(const int* __restrict__ col) {
    int e = blockIdx.x * blockDim.x + threadIdx.x;
    if (e < Ee) atomicAdd(&g_dis[col[e]], 1.0f);
}

__global__ void deg_fin_counts_kernel(const int* __restrict__ batch) {
    int n = blockIdx.x * blockDim.x + threadIdx.x;
    if (n < Nn) {
        g_dis[n] = rsqrtf(g_dis[n]);
        atomicAdd(&g_counts[batch[n]], 1);
    }
}

// ---------------- exclusive scan over 1024 counts (one block) ---------------
__global__ void scan_kernel() {
    __shared__ int sbuf[Bb];
    int tid = threadIdx.x;
    int c = g_counts[tid];
    sbuf[tid] = c;
    __syncthreads();
    for (int off = 1; off < Bb; off <<= 1) {
        int v = (tid >= off) ? sbuf[tid - off] : 0;
        __syncthreads();
        sbuf[tid] += v;
        __syncthreads();
    }
    g_starts[tid] = sbuf[tid] - c;   // exclusive
}

// ---------------- layer-0 aggregation (one-hot collapse) --------------------
__global__ void agg0_zero_kernel() {
    int i = blockIdx.x * blockDim.x + threadIdx.x;
    if (i < Nn * (HID / 4)) ((float4*)g_Agg)[i] = make_float4(0.f, 0.f, 0.f, 0.f);
}
__global__ void agg0_self_kernel(const int* __restrict__ z) {
    int n = blockIdx.x * blockDim.x + threadIdx.x;
    if (n < Nn) {
        float d = g_dis[n];
        g_Agg[(size_t)n * HID + z[n]] = d * d;
    }
}
__global__ void agg0_edges_kernel(const int* __restrict__ row, const int* __restrict__ col,
                                  const int* __restrict__ z) {
    int e = blockIdx.x * blockDim.x + threadIdx.x;
    if (e >= Ee) return;
    int r = row[e], c = col[e];
    atomicAdd(&g_Agg[(size_t)c * HID + z[r]], g_dis[r] * g_dis[c]);
}

// ---------------- layers 1/2 aggregation ------------------------------------
// self-loop init: Agg[n] = X[n, off:off+128] * dis[n]^2
__global__ void agg_init12_kernel(int off) {
    int i = blockIdx.x * blockDim.x + threadIdx.x;
    if (i >= Nn * (HID / 4)) return;
    int n = i >> 5, q = i & 31;
    float d = g_dis[n];
    float w = d * d;
    float4 v = *(const float4*)(g_X + (size_t)n * DD + off + q * 4);
    v.x *= w; v.y *= w; v.z *= w; v.w *= w;
    ((float4*)(g_Agg + (size_t)n * HID))[q] = v;
}

// warp per edge: gather 128 floats of source, scale, atomic-add into target
__global__ void agg_edges12_kernel(const int* __restrict__ row, const int* __restrict__ col,
                                   int off) {
    int gt = blockIdx.x * blockDim.x + threadIdx.x;
    int e = gt >> 5;
    if (e >= Ee) return;
    int lane = gt & 31;
    int r = row[e], c = col[e];        // same-address loads coalesce to broadcast
    float w = g_dis[r] * g_dis[c];
    float4 v = *(const float4*)(g_X + (size_t)r * DD + off + lane * 4);
    float* dst = g_Agg + (size_t)c * HID + lane * 4;
    atomicAdd(dst + 0, v.x * w);
    atomicAdd(dst + 1, v.y * w);
    atomicAdd(dst + 2, v.z * w);
    atomicAdd(dst + 3, v.w * w);
}

// ---------------- GEMM (N x 128) @ (128 x 128) with fused bias+tanh ---------
// A = g_Agg (stride 128). Out = g_X + out_off (stride 384).
// Tile 64 rows x 128 cols, 128 threads, 8x8 per-thread register tile.
__global__ void __launch_bounds__(128) gemm_tanh_kernel(const float* __restrict__ W,
                                                        const float* __restrict__ bias,
                                                        int out_off) {
    __shared__ float As[64 * 128];
    __shared__ float Ws[16 * 128];
    int t = threadIdx.x;
    int rbase = blockIdx.x * 64;
    int tx = t & 15, ty = t >> 4;
    int col0 = tx * 8, row0 = ty * 8;

    // load A tile (contiguous 64*128 floats)
    const float4* A4 = (const float4*)(g_Agg + (size_t)rbase * HID);
    float4* As4 = (float4*)As;
    #pragma unroll
    for (int i = 0; i < 16; ++i) As4[t + i * 128] = A4[t + i * 128];

    float acc[8][8];
    #pragma unroll
    for (int i = 0; i < 8; ++i)
        #pragma unroll
        for (int j = 0; j < 8; ++j) acc[i][j] = 0.f;

    float4* Ws4 = (float4*)Ws;
    for (int kc = 0; kc < 8; ++kc) {
        __syncthreads();                                     // also covers As load on kc==0
        const float4* W4 = (const float4*)(W + kc * 16 * 128);
        #pragma unroll
        for (int i = 0; i < 4; ++i) Ws4[t + i * 128] = W4[t + i * 128];
        __syncthreads();
        #pragma unroll
        for (int k = 0; k < 16; ++k) {
            float a[8];
            #pragma unroll
            for (int i = 0; i < 8; ++i) a[i] = As[(row0 + i) * 128 + kc * 16 + k];
            float4 w0 = Ws4[k * 32 + tx * 2];
            float4 w1 = Ws4[k * 32 + tx * 2 + 1];
            float wv[8] = {w0.x, w0.y, w0.z, w0.w, w1.x, w1.y, w1.z, w1.w};
            #pragma unroll
            for (int i = 0; i < 8; ++i)
                #pragma unroll
                for (int j = 0; j < 8; ++j) acc[i][j] = fmaf(a[i], wv[j], acc[i][j]);
        }
    }
    float bv[8];
    #pragma unroll
    for (int j = 0; j < 8; ++j) bv[j] = __ldg(&bias[col0 + j]);
    #pragma unroll
    for (int i = 0; i < 8; ++i) {
        int rown = rbase + row0 + i;
        float* o = g_X + (size_t)rown * DD + out_off + col0;
        #pragma unroll
        for (int j = 0; j < 8; ++j) o[j] = tanhf(acc[i][j] + bv[j]);
    }
}

// ---------------- per-graph head: sort-pool + conv1 + conv2 + pool + fc -----
__global__ void __launch_bounds__(256) head_kernel(
        const float* __restrict__ Wc1, const float* __restrict__ bc1,
        const float* __restrict__ Wc2, const float* __restrict__ bc2,
        const float* __restrict__ g1,  const float* __restrict__ be1,
        const float* __restrict__ g2,  const float* __restrict__ be2,
        const float* __restrict__ Wl1, const float* __restrict__ bl1,
        const float* __restrict__ Wl2, const float* __restrict__ bl2,
        const float* __restrict__ rm1, const float* __restrict__ rv1,
        const float* __restrict__ rm2, const float* __restrict__ rv2,
        float* __restrict__ out) {
    __shared__ float keys[SMAX];
    __shared__ int   topk[KK];
    __shared__ float Wc1s[C1n * DD];
    __shared__ float c1s[C1n * KK];
    __shared__ float h2s[C2n * L2n];
    __shared__ float ps[FLAT];            // [oc*PL + l] == flat order
    __shared__ float f1[128];
    __shared__ float red[256];

    int b = blockIdx.x, tid = threadIdx.x, bd = blockDim.x;
    int M = g_counts[b];
    if (M > SMAX) M = SMAX;               // astronomically unlikely
    int s = g_starts[b];

    for (int i = tid; i < C1n * DD; i += bd) Wc1s[i] = Wc1[i];
    for (int i = tid; i < M; i += bd) keys[i] = g_X[(size_t)(s + i) * DD + (DD - 1)];
    for (int i = tid; i < KK; i += bd) topk[i] = -1;
    __syncthreads();

    // stable rank: (key desc, index asc) — replicates jnp.lexsort stability
    for (int i = tid; i < M; i += bd) {
        float ki = keys[i];
        int r = 0;
        for (int j = 0; j < M; ++j) {
            float kj = keys[j];
            r += (kj > ki) || (kj == ki && j < i);
        }
        if (r < KK) topk[r] = s + i;
    }
    __syncthreads();

    // conv1 (dense over D per kept node) + relu + bn1
    for (int o = tid; o < C1n * KK; o += bd) {
        int c = o & 15, k = o >> 4;       // 16 threads share node row -> L1 broadcast
        int node = topk[k];
        float acc = __ldg(&bc1[c]);
        if (node >= 0) {
            const float* xr = g_X + (size_t)node * DD;
            const float* w = Wc1s + c * DD;
            #pragma unroll 4
            for (int d = 0; d < DD; ++d) acc += xr[d] * w[d];
        }
        float v = fmaxf(acc, 0.f);
        v = (v - __ldg(&rm1[c])) * (__ldg(&g1[c]) * rsqrtf(__ldg(&rv1[c]) + EPSc)) + __ldg(&be1[c]);
        c1s[c * KK + k] = v;
    }
    __syncthreads();

    // conv2 (k=5) + relu + bn2
    for (int o = tid; o < C2n * L2n; o += bd) {
        int oc = o / L2n, tt = o % L2n;
        float acc = __ldg(&bc2[oc]);
        const float* w = Wc2 + oc * (C1n * KERNL);
        for (int ic = 0; ic < C1n; ++ic) {
            #pragma unroll
            for (int kk = 0; kk < KERNL; ++kk)
                acc += c1s[ic * KK + tt + kk] * __ldg(&w[ic * KERNL + kk]);
        }
        float v = fmaxf(acc, 0.f);
        v = (v - __ldg(&rm2[oc])) * (__ldg(&g2[oc]) * rsqrtf(__ldg(&rv2[oc]) + EPSc)) + __ldg(&be2[oc]);
        h2s[oc * L2n + tt] = v;
    }
    __syncthreads();

    // maxpool(2,2)
    for (int o = tid; o < FLAT; o += bd) {
        int oc = o / PL, l = o % PL;
        ps[o] = fmaxf(h2s[oc * L2n + 2 * l], h2s[oc * L2n + 2 * l + 1]);
    }
    __syncthreads();

    // fc1 (416 -> 128) + relu
    for (int j = tid; j < 128; j += bd) {
        float acc = __ldg(&bl1[j]);
        const float* w = Wl1 + j * FLAT;
        #pragma unroll 4
        for (int i = 0; i < FLAT; ++i) acc += ps[i] * __ldg(&w[i]);
        f1[j] = fmaxf(acc, 0.f);
    }
    __syncthreads();

    // fc2 (128 -> 1)
    float p = 0.f;
    if (tid < 128) p = f1[tid] * __ldg(&Wl2[tid]);
    red[tid] = p;
    __syncthreads();
    for (int off = 128; off > 0; off >>= 1) {
        if (tid < off && tid + off < bd) red[tid] += red[tid + off];
        __syncthreads();
    }
    if (tid == 0) out[b] = red[0] + __ldg(&bl2[0]);
}

// ---------------- host orchestration ----------------------------------------
extern "C" void kernel_launch(void* const* d_in, const int* in_sizes, int n_in,
                              void* d_out, int out_size) {
    const int*   z     = (const int*)d_in[0];
    const int*   ei    = (const int*)d_in[1];
    const int*   batch = (const int*)d_in[2];
    const float* W0    = (const float*)d_in[3];
    const float* b0    = (const float*)d_in[4];
    const float* W1    = (const float*)d_in[5];
    const float* b1    = (const float*)d_in[6];
    const float* W2    = (const float*)d_in[7];
    const float* b2    = (const float*)d_in[8];
    const float* Wc1   = (const float*)d_in[9];
    const float* bc1   = (const float*)d_in[10];
    const float* Wc2   = (const float*)d_in[11];
    const float* bc2   = (const float*)d_in[12];
    const float* g1    = (const float*)d_in[13];
    const float* be1   = (const float*)d_in[14];
    const float* g2    = (const float*)d_in[15];
    const float* be2   = (const float*)d_in[16];
    const float* Wl1   = (const float*)d_in[17];
    const float* bl1   = (const float*)d_in[18];
    const float* Wl2   = (const float*)d_in[19];
    const float* bl2   = (const float*)d_in[20];
    const float* rm1   = (const float*)d_in[21];
    const float* rv1   = (const float*)d_in[22];
    const float* rm2   = (const float*)d_in[23];
    const float* rv2   = (const float*)d_in[24];
    float* out = (float*)d_out;

    const int* row = ei;
    const int* col = ei + Ee;

    // degrees + per-graph counts/starts
    init_misc_kernel<<<(Nn + 255) / 256, 256>>>();
    deg_edges_kernel<<<(Ee + 255) / 256, 256>>>(col);
    deg_fin_counts_kernel<<<(Nn + 255) / 256, 256>>>(batch);
    scan_kernel<<<1, Bb>>>();

    // layer 0: one-hot aggregation (scalar scatter) then GEMM+tanh
    agg0_zero_kernel<<<(Nn * 32 + 255) / 256, 256>>>();
    agg0_self_kernel<<<(Nn + 255) / 256, 256>>>(z);
    agg0_edges_kernel<<<(Ee + 255) / 256, 256>>>(row, col, z);
    gemm_tanh_kernel<<<Nn / 64, 128>>>(W0, b0, 0);

    // layer 1
    agg_init12_kernel<<<(Nn * 32 + 255) / 256, 256>>>(0);
    agg_edges12_kernel<<<(Ee * 32 + 255) / 256, 256>>>(row, col, 0);
    gemm_tanh_kernel<<<Nn / 64, 128>>>(W1, b1, HID);

    // layer 2
    agg_init12_kernel<<<(Nn * 32 + 255) / 256, 256>>>(HID);
    agg_edges12_kernel<<<(Ee * 32 + 255) / 256, 256>>>(row, col, HID);
    gemm_tanh_kernel<<<Nn / 64, 128>>>(W2, b2, 2 * HID);

    // sort-pool + conv head
    head_kernel<<<Bb, 256>>>(Wc1, bc1, Wc2, bc2, g1, be1, g2, be2,
                             Wl1, bl1, Wl2, bl2, rm1, rv1, rm2, rv2, out);
}

// round 2
// speedup vs baseline: 1.0764x; 1.0764x over previous
#include <cuda_runtime.h>
#include <math.h>

// Problem constants
#define Nn   131072
#define Ee   1048576
#define Bb   1024
#define FIN  128
#define HID  128
#define DD   384
#define KK   30
#define C1n  16
#define C2n  32
#define KERNL 5
#define L2n  26
#define PL   13
#define FLAT 416
#define EPSc 1e-5f
#define SMAX 2048

// packed fp32x2 helpers
#define PACKF2(out, lo, hi) \
    asm("mov.b64 %0, {%1, %2};" : "=l"(out) : "r"(__float_as_uint(lo)), "r"(__float_as_uint(hi)))
#define UNPACKF2(lo, hi, in) \
    { unsigned int _a, _b; asm("mov.b64 {%0, %1}, %2;" : "=r"(_a), "=r"(_b) : "l"(in)); \
      lo = __uint_as_float(_a); hi = __uint_as_float(_b); }
#define FMAF2(acc, a, b) \
    asm("fma.rn.f32x2 %0, %1, %2, %0;" : "+l"(acc) : "l"(a), "l"(b))

// ---------------- scratch ----------------------------------------------------
__device__ float g_dis[Nn];
__device__ int   g_cnt[Nn];
__device__ int   g_offs[Nn + 1];
__device__ int   g_cursor[Nn];
__device__ int   g_csr[Ee];
__device__ float g_Agg[(size_t)Nn * HID];
__device__ float g_Y[(size_t)Nn * HID];
__device__ float g_X[(size_t)Nn * DD];
__device__ int   g_bcnt[Bb];
__device__ int   g_starts[Bb];

// ---------------- init -------------------------------------------------------
__global__ void init_kernel() {
    int i = blockIdx.x * blockDim.x + threadIdx.x;
    if (i < Nn) g_cnt[i] = 0;
    if (i < Bb) g_bcnt[i] = 0;
}

// per-edge degree counts + per-node batch counts
__global__ void count_kernel(const int* __restrict__ col, const int* __restrict__ batch) {
    int e = blockIdx.x * blockDim.x + threadIdx.x;
    if (e < Ee) atomicAdd(&g_cnt[col[e]], 1);
    if (e < Nn) atomicAdd(&g_bcnt[batch[e]], 1);
}

// single-block scan over node counts -> offsets, cursor, dis
__global__ void scan_nodes_kernel() {
    __shared__ int sbuf[1024];
    int tid = threadIdx.x;
    int base = tid * 128;
    int s = 0;
    #pragma unroll 8
    for (int i = 0; i < 128; ++i) s += g_cnt[base + i];
    sbuf[tid] = s;
    __syncthreads();
    for (int off = 1; off < 1024; off <<= 1) {
        int v = (tid >= off) ? sbuf[tid - off] : 0;
        __syncthreads();
        sbuf[tid] += v;
        __syncthreads();
    }
    int run = sbuf[tid] - s;   // exclusive
    for (int i = 0; i < 128; ++i) {
        int c = g_cnt[base + i];
        g_offs[base + i] = run;
        g_cursor[base + i] = run;
        g_dis[base + i] = rsqrtf((float)(c + 1));
        run += c;
    }
    if (tid == 1023) g_offs[Nn] = run;
}

__global__ void scan_batch_kernel() {
    __shared__ int sbuf[Bb];
    int tid = threadIdx.x;
    int c = g_bcnt[tid];
    sbuf[tid] = c;
    __syncthreads();
    for (int off = 1; off < Bb; off <<= 1) {
        int v = (tid >= off) ? sbuf[tid - off] : 0;
        __syncthreads();
        sbuf[tid] += v;
        __syncthreads();
    }
    g_starts[tid] = sbuf[tid] - c;
}

// scatter edge source ids into CSR
__global__ void fill_kernel(const int* __restrict__ row, const int* __restrict__ col) {
    int e = blockIdx.x * blockDim.x + threadIdx.x;
    if (e >= Ee) return;
    int p = atomicAdd(&g_cursor[col[e]], 1);
    g_csr[p] = row[e];
}

// ---------------- layer-0 aggregation: per-node one-hot histogram -----------
__global__ void __launch_bounds__(256) agg0_kernel(const int* __restrict__ z) {
    __shared__ float bins[8][128];
    int w = threadIdx.x >> 5, lane = threadIdx.x & 31;
    int n = blockIdx.x * 8 + w;
    ((float4*)bins[w])[lane] = make_float4(0.f, 0.f, 0.f, 0.f);
    __syncwarp();
    int s = g_offs[n], e = g_offs[n + 1];
    for (int j = s + lane; j < e; j += 32) {
        int r = g_csr[j];
        atomicAdd(&bins[w][z[r]], g_dis[r]);
    }
    __syncwarp();
    if (lane == 0) bins[w][z[n]] += g_dis[n];
    __syncwarp();
    float dc = g_dis[n];
    float4 b = ((float4*)bins[w])[lane];
    b.x *= dc; b.y *= dc; b.z *= dc; b.w *= dc;
    ((float4*)(g_Agg + (size_t)n * HID))[lane] = b;
}

// ---------------- layers 1/2: CSR gather of pre-scaled rows -----------------
__global__ void __launch_bounds__(256) gather_kernel() {
    int gt = blockIdx.x * blockDim.x + threadIdx.x;
    int n = gt >> 5, lane = gt & 31;
    const float4* Y4 = (const float4*)g_Y;
    float4 acc = Y4[(size_t)n * 32 + lane];     // self term (pre-scaled by dis[n])
    int s = g_offs[n], e = g_offs[n + 1];
    int r = (s < e) ? g_csr[s] : 0;
    for (int j = s; j < e; ++j) {
        int rn = (j + 1 < e) ? g_csr[j + 1] : 0;
        float4 v = Y4[(size_t)r * 32 + lane];
        acc.x += v.x; acc.y += v.y; acc.z += v.z; acc.w += v.w;
        r = rn;
    }
    float dc = g_dis[n];
    acc.x *= dc; acc.y *= dc; acc.z *= dc; acc.w *= dc;
    ((float4*)(g_Agg))[(size_t)n * 32 + lane] = acc;
}

// ---------------- GEMM (N x 128) @ (128 x 128), fused bias+tanh, f32x2 ------
// writes X (stride 384 at out_off) and, if writeY, Y = tanh * dis (stride 128)
__global__ void __launch_bounds__(128) gemm_tanh_kernel(const float* __restrict__ W,
                                                        const float* __restrict__ bias,
                                                        int out_off, int writeY) {
    __shared__ float As[64 * 132];
    __shared__ float Ws[16 * 128];
    int t = threadIdx.x;
    int rbase = blockIdx.x * 64;
    int tx = t & 15, ty = t >> 4;
    int col0 = tx * 8, row0 = ty * 8;

    // load A tile into padded smem (row stride 132)
    {
        const float4* A4 = (const float4*)(g_Agg + (size_t)rbase * HID);
        #pragma unroll
        for (int i = 0; i < 16; ++i) {
            int idx = t + i * 128;
            int r = idx >> 5, c4 = idx & 31;
            *(float4*)(As + r * 132 + c4 * 4) = A4[idx];
        }
    }

    unsigned long long acc[8][4];
    #pragma unroll
    for (int i = 0; i < 8; ++i)
        #pragma unroll
        for (int j = 0; j < 4; ++j) acc[i][j] = 0ull;

    float4* Ws4 = (float4*)Ws;
    for (int kc = 0; kc < 8; ++kc) {
        __syncthreads();
        const float4* W4 = (const float4*)(W + kc * 16 * 128);
        #pragma unroll
        for (int i = 0; i < 4; ++i) Ws4[t + i * 128] = W4[t + i * 128];
        __syncthreads();
        #pragma unroll
        for (int k = 0; k < 16; ++k) {
            unsigned long long ad[8];
            #pragma unroll
            for (int i = 0; i < 8; ++i) {
                float a = As[(row0 + i) * 132 + kc * 16 + k];
                PACKF2(ad[i], a, a);
            }
            float4 w0 = *(const float4*)(Ws + k * 128 + col0);
            float4 w1 = *(const float4*)(Ws + k * 128 + col0 + 4);
            unsigned long long wp[4];
            PACKF2(wp[0], w0.x, w0.y);
            PACKF2(wp[1], w0.z, w0.w);
            PACKF2(wp[2], w1.x, w1.y);
            PACKF2(wp[3], w1.z, w1.w);
            #pragma unroll
            for (int i = 0; i < 8; ++i)
                #pragma unroll
                for (int j = 0; j < 4; ++j) FMAF2(acc[i][j], ad[i], wp[j]);
        }
    }

    float bv[8];
    #pragma unroll
    for (int j = 0; j < 8; ++j) bv[j] = __ldg(&bias[col0 + j]);
    #pragma unroll
    for (int i = 0; i < 8; ++i) {
        int rown = rbase + row0 + i;
        float dr = g_dis[rown];
        float v[8];
        #pragma unroll
        for (int j = 0; j < 4; ++j) { UNPACKF2(v[2*j], v[2*j+1], acc[i][j]); }
        #pragma unroll
        for (int j = 0; j < 8; ++j) v[j] = tanhf(v[j] + bv[j]);
        float* o = g_X + (size_t)rown * DD + out_off + col0;
        *(float4*)(o)     = make_float4(v[0], v[1], v[2], v[3]);
        *(float4*)(o + 4) = make_float4(v[4], v[5], v[6], v[7]);
        if (writeY) {
            float* y = g_Y + (size_t)rown * HID + col0;
            *(float4*)(y)     = make_float4(v[0]*dr, v[1]*dr, v[2]*dr, v[3]*dr);
            *(float4*)(y + 4) = make_float4(v[4]*dr, v[5]*dr, v[6]*dr, v[7]*dr);
        }
    }
}

// ---------------- per-graph head --------------------------------------------
__global__ void __launch_bounds__(256) head_kernel(
        const float* __restrict__ Wc1, const float* __restrict__ bc1,
        const float* __restrict__ Wc2, const float* __restrict__ bc2,
        const float* __restrict__ g1,  const float* __restrict__ be1,
        const float* __restrict__ g2,  const float* __restrict__ be2,
        const float* __restrict__ Wl1, const float* __restrict__ bl1,
        const float* __restrict__ Wl2, const float* __restrict__ bl2,
        const float* __restrict__ rm1, const float* __restrict__ rv1,
        const float* __restrict__ rm2, const float* __restrict__ rv2,
        float* __restrict__ out) {
    __shared__ float keys[SMAX];
    __shared__ int   topk[KK];
    __shared__ float Wc1s[C1n * DD];
    __shared__ float c1s[C1n * KK];
    __shared__ float h2s[C2n * L2n];
    __shared__ float ps[FLAT];
    __shared__ float f1[128];
    __shared__ float red[256];

    int b = blockIdx.x, tid = threadIdx.x, bd = blockDim.x;
    int M = g_bcnt[b];
    if (M > SMAX) M = SMAX;
    int s = g_starts[b];

    for (int i = tid; i < C1n * DD; i += bd) Wc1s[i] = Wc1[i];
    for (int i = tid; i < M; i += bd) keys[i] = g_X[(size_t)(s + i) * DD + (DD - 1)];
    for (int i = tid; i < KK; i += bd) topk[i] = -1;
    __syncthreads();

    // stable rank (key desc, index asc)
    for (int i = tid; i < M; i += bd) {
        float ki = keys[i];
        int r = 0;
        for (int j = 0; j < M; ++j) {
            float kj = keys[j];
            r += (kj > ki) || (kj == ki && j < i);
        }
        if (r < KK) topk[r] = s + i;
    }
    __syncthreads();

    // conv1 + relu + bn1
    for (int o = tid; o < C1n * KK; o += bd) {
        int c = o & 15, k = o >> 4;
        int node = topk[k];
        float acc = __ldg(&bc1[c]);
        if (node >= 0) {
            const float* xr = g_X + (size_t)node * DD;
            const float* w = Wc1s + c * DD;
            #pragma unroll 4
            for (int d = 0; d < DD; ++d) acc += xr[d] * w[d];
        }
        float v = fmaxf(acc, 0.f);
        v = (v - __ldg(&rm1[c])) * (__ldg(&g1[c]) * rsqrtf(__ldg(&rv1[c]) + EPSc)) + __ldg(&be1[c]);
        c1s[c * KK + k] = v;
    }
    __syncthreads();

    // conv2 + relu + bn2
    for (int o = tid; o < C2n * L2n; o += bd) {
        int oc = o / L2n, tt = o % L2n;
        float acc = __ldg(&bc2[oc]);
        const float* w = Wc2 + oc * (C1n * KERNL);
        for (int ic = 0; ic < C1n; ++ic) {
            #pragma unroll
            for (int kk = 0; kk < KERNL; ++kk)
                acc += c1s[ic * KK + tt + kk] * __ldg(&w[ic * KERNL + kk]);
        }
        float v = fmaxf(acc, 0.f);
        v = (v - __ldg(&rm2[oc])) * (__ldg(&g2[oc]) * rsqrtf(__ldg(&rv2[oc]) + EPSc)) + __ldg(&be2[oc]);
        h2s[oc * L2n + tt] = v;
    }
    __syncthreads();

    for (int o = tid; o < FLAT; o += bd) {
        int oc = o / PL, l = o % PL;
        ps[o] = fmaxf(h2s[oc * L2n + 2 * l], h2s[oc * L2n + 2 * l + 1]);
    }
    __syncthreads();

    for (int j = tid; j < 128; j += bd) {
        float acc = __ldg(&bl1[j]);
        const float* w = Wl1 + j * FLAT;
        #pragma unroll 4
        for (int i = 0; i < FLAT; ++i) acc += ps[i] * __ldg(&w[i]);
        f1[j] = fmaxf(acc, 0.f);
    }
    __syncthreads();

    float p = 0.f;
    if (tid < 128) p = f1[tid] * __ldg(&Wl2[tid]);
    red[tid] = p;
    __syncthreads();
    for (int off = 128; off > 0; off >>= 1) {
        if (tid < off && tid + off < bd) red[tid] += red[tid + off];
        __syncthreads();
    }
    if (tid == 0) out[b] = red[0] + __ldg(&bl2[0]);
}

// ---------------- host orchestration ----------------------------------------
extern "C" void kernel_launch(void* const* d_in, const int* in_sizes, int n_in,
                              void* d_out, int out_size) {
    const int*   z     = (const int*)d_in[0];
    const int*   ei    = (const int*)d_in[1];
    const int*   batch = (const int*)d_in[2];
    const float* W0    = (const float*)d_in[3];
    const float* b0    = (const float*)d_in[4];
    const float* W1    = (const float*)d_in[5];
    const float* b1    = (const float*)d_in[6];
    const float* W2    = (const float*)d_in[7];
    const float* b2    = (const float*)d_in[8];
    const float* Wc1   = (const float*)d_in[9];
    const float* bc1   = (const float*)d_in[10];
    const float* Wc2   = (const float*)d_in[11];
    const float* bc2   = (const float*)d_in[12];
    const float* g1    = (const float*)d_in[13];
    const float* be1   = (const float*)d_in[14];
    const float* g2    = (const float*)d_in[15];
    const float* be2   = (const float*)d_in[16];
    const float* Wl1   = (const float*)d_in[17];
    const float* bl1   = (const float*)d_in[18];
    const float* Wl2   = (const float*)d_in[19];
    const float* bl2   = (const float*)d_in[20];
    const float* rm1   = (const float*)d_in[21];
    const float* rv1   = (const float*)d_in[22];
    const float* rm2   = (const float*)d_in[23];
    const float* rv2   = (const float*)d_in[24];
    float* out = (float*)d_out;

    const int* row = ei;
    const int* col = ei + Ee;

    init_kernel<<<(Nn + 255) / 256, 256>>>();
    count_kernel<<<(Ee + 255) / 256, 256>>>(col, batch);
    scan_nodes_kernel<<<1, 1024>>>();
    scan_batch_kernel<<<1, Bb>>>();
    fill_kernel<<<(Ee + 255) / 256, 256>>>(row, col);

    // layer 0
    agg0_kernel<<<Nn / 8, 256>>>(z);
    gemm_tanh_kernel<<<Nn / 64, 128>>>(W0, b0, 0, 1);

    // layer 1
    gather_kernel<<<Nn * 32 / 256, 256>>>();
    gemm_tanh_kernel<<<Nn / 64, 128>>>(W1, b1, HID, 1);

    // layer 2
    gather_kernel<<<Nn * 32 / 256, 256>>>();
    gemm_tanh_kernel<<<Nn / 64, 128>>>(W2, b2, 2 * HID, 0);

    head_kernel<<<Bb, 256>>>(Wc1, bc1, Wc2, bc2, g1, be1, g2, be2,
                             Wl1, bl1, Wl2, bl2, rm1, rv1, rm2, rv2, out);
}

// round 3
// speedup vs baseline: 1.4383x; 1.3361x over previous
#include <cuda_runtime.h>
#include <math.h>

// Problem constants
#define Nn   131072
#define Ee   1048576
#define Bb   1024
#define FIN  128
#define HID  128
#define DD   384
#define KK   30
#define C1n  16
#define C2n  32
#define KERNL 5
#define L2n  26
#define PL   13
#define FLAT 416
#define EPSc 1e-5f
#define SMAX 2048
#define SCANB 512   // scan blocks (512*256 = 131072)

// packed fp32x2 helpers
#define PACKF2(out, lo, hi) \
    asm("mov.b64 %0, {%1, %2};" : "=l"(out) : "r"(__float_as_uint(lo)), "r"(__float_as_uint(hi)))
#define UNPACKF2(lo, hi, in) \
    { unsigned int _a, _b; asm("mov.b64 {%0, %1}, %2;" : "=r"(_a), "=r"(_b) : "l"(in)); \
      lo = __uint_as_float(_a); hi = __uint_as_float(_b); }
#define FMAF2(acc, a, b) \
    asm("fma.rn.f32x2 %0, %1, %2, %0;" : "+l"(acc) : "l"(a), "l"(b))

// ---------------- scratch ----------------------------------------------------
__device__ float g_dis[Nn];
__device__ int   g_cnt[Nn];
__device__ int   g_offs[Nn + 1];
__device__ int   g_cursor[Nn];
__device__ int   g_csr[Ee];
__device__ float g_Agg[(size_t)Nn * HID];
__device__ float g_Y[(size_t)Nn * HID];
__device__ float g_X[(size_t)Nn * DD];
__device__ int   g_bcnt[Bb];
__device__ int   g_starts[Bb];
__device__ int   g_bsum[SCANB];
__device__ int   g_bbase[SCANB];

// ---------------- init -------------------------------------------------------
__global__ void init_kernel() {
    int i = blockIdx.x * blockDim.x + threadIdx.x;
    if (i < Nn) g_cnt[i] = 0;
    if (i < Bb) g_bcnt[i] = 0;
}

__global__ void count_kernel(const int* __restrict__ col, const int* __restrict__ batch) {
    int e = blockIdx.x * blockDim.x + threadIdx.x;
    if (e < Ee) atomicAdd(&g_cnt[col[e]], 1);
    if (e < Nn) atomicAdd(&g_bcnt[batch[e]], 1);
}

// ---------------- hierarchical scan over node counts (coalesced) ------------
__global__ void scanA_kernel() {
    __shared__ int s[256];
    int tid = threadIdx.x;
    int i = blockIdx.x * 256 + tid;
    int c = g_cnt[i];
    s[tid] = c;
    __syncthreads();
    #pragma unroll
    for (int off = 1; off < 256; off <<= 1) {
        int v = (tid >= off) ? s[tid - off] : 0;
        __syncthreads();
        s[tid] += v;
        __syncthreads();
    }
    g_offs[i] = s[tid] - c;                 // block-local exclusive
    if (tid == 255) g_bsum[blockIdx.x] = s[255];
}

__global__ void scanB_kernel() {
    __shared__ int s[SCANB];
    int tid = threadIdx.x;
    int c = g_bsum[tid];
    s[tid] = c;
    __syncthreads();
    for (int off = 1; off < SCANB; off <<= 1) {
        int v = (tid >= off) ? s[tid - off] : 0;
        __syncthreads();
        s[tid] += v;
        __syncthreads();
    }
    g_bbase[tid] = s[tid] - c;              // exclusive block base
}

__global__ void scanC_kernel() {
    int tid = threadIdx.x;
    int i = blockIdx.x * 256 + tid;
    int o = g_offs[i] + g_bbase[blockIdx.x];
    g_offs[i] = o;
    g_cursor[i] = o;
    g_dis[i] = rsqrtf((float)(g_cnt[i] + 1));
    if (i == 0) g_offs[Nn] = Ee;
}

__global__ void scan_batch_kernel() {
    __shared__ int sbuf[Bb];
    int tid = threadIdx.x;
    int c = g_bcnt[tid];
    sbuf[tid] = c;
    __syncthreads();
    for (int off = 1; off < Bb; off <<= 1) {
        int v = (tid >= off) ? sbuf[tid - off] : 0;
        __syncthreads();
        sbuf[tid] += v;
        __syncthreads();
    }
    g_starts[tid] = sbuf[tid] - c;
}

__global__ void fill_kernel(const int* __restrict__ row, const int* __restrict__ col) {
    int e = blockIdx.x * blockDim.x + threadIdx.x;
    if (e >= Ee) return;
    int p = atomicAdd(&g_cursor[col[e]], 1);
    g_csr[p] = row[e];
}

// ---------------- layer-0 aggregation: per-node one-hot histogram -----------
__global__ void __launch_bounds__(256) agg0_kernel(const int* __restrict__ z) {
    __shared__ float bins[8][128];
    int w = threadIdx.x >> 5, lane = threadIdx.x & 31;
    int n = blockIdx.x * 8 + w;
    ((float4*)bins[w])[lane] = make_float4(0.f, 0.f, 0.f, 0.f);
    __syncwarp();
    int s = g_offs[n], e = g_offs[n + 1];
    for (int j = s + lane; j < e; j += 32) {
        int r = g_csr[j];
        atomicAdd(&bins[w][z[r]], g_dis[r]);
    }
    __syncwarp();
    if (lane == 0) bins[w][z[n]] += g_dis[n];
    __syncwarp();
    float dc = g_dis[n];
    float4 b = ((float4*)bins[w])[lane];
    b.x *= dc; b.y *= dc; b.z *= dc; b.w *= dc;
    ((float4*)(g_Agg + (size_t)n * HID))[lane] = b;
}

// ---------------- layers 1/2: CSR gather of pre-scaled rows -----------------
__global__ void __launch_bounds__(256) gather_kernel() {
    int gt = blockIdx.x * blockDim.x + threadIdx.x;
    int n = gt >> 5, lane = gt & 31;
    const float4* Y4 = (const float4*)g_Y;
    float4 acc = Y4[(size_t)n * 32 + lane];
    float4 acc2 = make_float4(0.f, 0.f, 0.f, 0.f);
    int s = g_offs[n], e = g_offs[n + 1];
    int j = s;
    for (; j + 2 <= e; j += 2) {
        int r0 = g_csr[j], r1 = g_csr[j + 1];
        float4 v0 = Y4[(size_t)r0 * 32 + lane];
        float4 v1 = Y4[(size_t)r1 * 32 + lane];
        acc.x += v0.x; acc.y += v0.y; acc.z += v0.z; acc.w += v0.w;
        acc2.x += v1.x; acc2.y += v1.y; acc2.z += v1.z; acc2.w += v1.w;
    }
    if (j < e) {
        int r = g_csr[j];
        float4 v = Y4[(size_t)r * 32 + lane];
        acc.x += v.x; acc.y += v.y; acc.z += v.z; acc.w += v.w;
    }
    acc.x += acc2.x; acc.y += acc2.y; acc.z += acc2.z; acc.w += acc2.w;
    float dc = g_dis[n];
    acc.x *= dc; acc.y *= dc; acc.z *= dc; acc.w *= dc;
    ((float4*)(g_Agg))[(size_t)n * 32 + lane] = acc;
}

// ---------------- GEMM (rows x 128) @ (128 x 128), fused bias+tanh, f32x2 ---
__global__ void __launch_bounds__(128) gemm_tanh_kernel(const float* __restrict__ W,
                                                        const float* __restrict__ bias,
                                                        int out_off, int writeY) {
    __shared__ float As[64 * 132];
    __shared__ float Ws[16 * 128];
    int t = threadIdx.x;
    int rbase = blockIdx.x * 64;
    int tx = t & 15, ty = t >> 4;
    int col0 = tx * 8, row0 = ty * 8;

    {
        const float4* A4 = (const float4*)(g_Agg + (size_t)rbase * HID);
        #pragma unroll
        for (int i = 0; i < 16; ++i) {
            int idx = t + i * 128;
            int r = idx >> 5, c4 = idx & 31;
            *(float4*)(As + r * 132 + c4 * 4) = A4[idx];
        }
    }

    unsigned long long acc[8][4];
    #pragma unroll
    for (int i = 0; i < 8; ++i)
        #pragma unroll
        for (int j = 0; j < 4; ++j) acc[i][j] = 0ull;

    float4* Ws4 = (float4*)Ws;
    for (int kc = 0; kc < 8; ++kc) {
        __syncthreads();
        const float4* W4 = (const float4*)(W + kc * 16 * 128);
        #pragma unroll
        for (int i = 0; i < 4; ++i) Ws4[t + i * 128] = W4[t + i * 128];
        __syncthreads();
        #pragma unroll
        for (int k = 0; k < 16; ++k) {
            unsigned long long ad[8];
            #pragma unroll
            for (int i = 0; i < 8; ++i) {
                float a = As[(row0 + i) * 132 + kc * 16 + k];
                PACKF2(ad[i], a, a);
            }
            // read W pairs directly as aligned 64-bit values (no repack)
            const unsigned long long* wrow =
                (const unsigned long long*)(Ws + k * 128 + col0);
            unsigned long long wp0 = wrow[0], wp1 = wrow[1],
                               wp2 = wrow[2], wp3 = wrow[3];
            #pragma unroll
            for (int i = 0; i < 8; ++i) {
                FMAF2(acc[i][0], ad[i], wp0);
                FMAF2(acc[i][1], ad[i], wp1);
                FMAF2(acc[i][2], ad[i], wp2);
                FMAF2(acc[i][3], ad[i], wp3);
            }
        }
    }

    float bv[8];
    #pragma unroll
    for (int j = 0; j < 8; ++j) bv[j] = __ldg(&bias[col0 + j]);
    #pragma unroll
    for (int i = 0; i < 8; ++i) {
        int rown = rbase + row0 + i;
        float dr = g_dis[rown];
        float v[8];
        #pragma unroll
        for (int j = 0; j < 4; ++j) { UNPACKF2(v[2*j], v[2*j+1], acc[i][j]); }
        #pragma unroll
        for (int j = 0; j < 8; ++j) v[j] = tanhf(v[j] + bv[j]);
        float* o = g_X + (size_t)rown * DD + out_off + col0;
        *(float4*)(o)     = make_float4(v[0], v[1], v[2], v[3]);
        *(float4*)(o + 4) = make_float4(v[4], v[5], v[6], v[7]);
        if (writeY) {
            float* y = g_Y + (size_t)rown * HID + col0;
            *(float4*)(y)     = make_float4(v[0]*dr, v[1]*dr, v[2]*dr, v[3]*dr);
            *(float4*)(y + 4) = make_float4(v[4]*dr, v[5]*dr, v[6]*dr, v[7]*dr);
        }
    }
}

// ---------------- per-graph head --------------------------------------------
__global__ void __launch_bounds__(256) head_kernel(
        const float* __restrict__ Wc1, const float* __restrict__ bc1,
        const float* __restrict__ Wc2, const float* __restrict__ bc2,
        const float* __restrict__ g1,  const float* __restrict__ be1,
        const float* __restrict__ g2,  const float* __restrict__ be2,
        const float* __restrict__ Wl1, const float* __restrict__ bl1,
        const float* __restrict__ Wl2, const float* __restrict__ bl2,
        const float* __restrict__ rm1, const float* __restrict__ rv1,
        const float* __restrict__ rm2, const float* __restrict__ rv2,
        float* __restrict__ out) {
    __shared__ float keys[SMAX];
    __shared__ int   topk[KK];
    __shared__ float Wc1s[C1n * DD];
    __shared__ float c1s[C1n * KK];
    __shared__ float h2s[C2n * L2n];
    __shared__ float ps[FLAT];
    __shared__ float f1[128];
    __shared__ float red[256];

    int b = blockIdx.x, tid = threadIdx.x, bd = blockDim.x;
    int M = g_bcnt[b];
    if (M > SMAX) M = SMAX;
    int s = g_starts[b];

    for (int i = tid; i < C1n * DD; i += bd) Wc1s[i] = Wc1[i];
    for (int i = tid; i < M; i += bd) keys[i] = g_X[(size_t)(s + i) * DD + (DD - 1)];
    for (int i = tid; i < KK; i += bd) topk[i] = -1;
    __syncthreads();

    for (int i = tid; i < M; i += bd) {
        float ki = keys[i];
        int r = 0;
        for (int j = 0; j < M; ++j) {
            float kj = keys[j];
            r += (kj > ki) || (kj == ki && j < i);
        }
        if (r < KK) topk[r] = s + i;
    }
    __syncthreads();

    for (int o = tid; o < C1n * KK; o += bd) {
        int c = o & 15, k = o >> 4;
        int node = topk[k];
        float acc = __ldg(&bc1[c]);
        if (node >= 0) {
            const float* xr = g_X + (size_t)node * DD;
            const float* w = Wc1s + c * DD;
            #pragma unroll 4
            for (int d = 0; d < DD; ++d) acc += xr[d] * w[d];
        }
        float v = fmaxf(acc, 0.f);
        v = (v - __ldg(&rm1[c])) * (__ldg(&g1[c]) * rsqrtf(__ldg(&rv1[c]) + EPSc)) + __ldg(&be1[c]);
        c1s[c * KK + k] = v;
    }
    __syncthreads();

    for (int o = tid; o < C2n * L2n; o += bd) {
        int oc = o / L2n, tt = o % L2n;
        float acc = __ldg(&bc2[oc]);
        const float* w = Wc2 + oc * (C1n * KERNL);
        for (int ic = 0; ic < C1n; ++ic) {
            #pragma unroll
            for (int kk = 0; kk < KERNL; ++kk)
                acc += c1s[ic * KK + tt + kk] * __ldg(&w[ic * KERNL + kk]);
        }
        float v = fmaxf(acc, 0.f);
        v = (v - __ldg(&rm2[oc])) * (__ldg(&g2[oc]) * rsqrtf(__ldg(&rv2[oc]) + EPSc)) + __ldg(&be2[oc]);
        h2s[oc * L2n + tt] = v;
    }
    __syncthreads();

    for (int o = tid; o < FLAT; o += bd) {
        int oc = o / PL, l = o % PL;
        ps[o] = fmaxf(h2s[oc * L2n + 2 * l], h2s[oc * L2n + 2 * l + 1]);
    }
    __syncthreads();

    for (int j = tid; j < 128; j += bd) {
        float acc = __ldg(&bl1[j]);
        const float* w = Wl1 + j * FLAT;
        #pragma unroll 4
        for (int i = 0; i < FLAT; ++i) acc += ps[i] * __ldg(&w[i]);
        f1[j] = fmaxf(acc, 0.f);
    }
    __syncthreads();

    float p = 0.f;
    if (tid < 128) p = f1[tid] * __ldg(&Wl2[tid]);
    red[tid] = p;
    __syncthreads();
    for (int off = 128; off > 0; off >>= 1) {
        if (tid < off && tid + off < bd) red[tid] += red[tid + off];
        __syncthreads();
    }
    if (tid == 0) out[b] = red[0] + __ldg(&bl2[0]);
}

// ---------------- host orchestration ----------------------------------------
extern "C" void kernel_launch(void* const* d_in, const int* in_sizes, int n_in,
                              void* d_out, int out_size) {
    const int*   z     = (const int*)d_in[0];
    const int*   ei    = (const int*)d_in[1];
    const int*   batch = (const int*)d_in[2];
    const float* W0    = (const float*)d_in[3];
    const float* b0    = (const float*)d_in[4];
    const float* W1    = (const float*)d_in[5];
    const float* b1    = (const float*)d_in[6];
    const float* W2    = (const float*)d_in[7];
    const float* b2    = (const float*)d_in[8];
    const float* Wc1   = (const float*)d_in[9];
    const float* bc1   = (const float*)d_in[10];
    const float* Wc2   = (const float*)d_in[11];
    const float* bc2   = (const float*)d_in[12];
    const float* g1    = (const float*)d_in[13];
    const float* be1   = (const float*)d_in[14];
    const float* g2    = (const float*)d_in[15];
    const float* be2   = (const float*)d_in[16];
    const float* Wl1   = (const float*)d_in[17];
    const float* bl1   = (const float*)d_in[18];
    const float* Wl2   = (const float*)d_in[19];
    const float* bl2   = (const float*)d_in[20];
    const float* rm1   = (const float*)d_in[21];
    const float* rv1   = (const float*)d_in[22];
    const float* rm2   = (const float*)d_in[23];
    const float* rv2   = (const float*)d_in[24];
    float* out = (float*)d_out;

    const int* row = ei;
    const int* col = ei + Ee;

    init_kernel<<<(Nn + 255) / 256, 256>>>();                 // 0
    count_kernel<<<(Ee + 255) / 256, 256>>>(col, batch);      // 1
    scanA_kernel<<<SCANB, 256>>>();                           // 2
    // PROBE at profiled slot (redundant quarter-size GEMM on scratch; its
    // outputs are fully overwritten by the real pipeline below).
    gemm_tanh_kernel<<<512, 128>>>(W0, b0, 0, 1);             // 3  <-- profiled
    scanB_kernel<<<1, SCANB>>>();                             // 4
    scanC_kernel<<<SCANB, 256>>>();                           // 5
    scan_batch_kernel<<<1, Bb>>>();                           // 6
    fill_kernel<<<(Ee + 255) / 256, 256>>>(row, col);         // 7

    agg0_kernel<<<Nn / 8, 256>>>(z);                          // 8
    gemm_tanh_kernel<<<Nn / 64, 128>>>(W0, b0, 0, 1);         // 9

    gather_kernel<<<Nn * 32 / 256, 256>>>();                  // 10
    gemm_tanh_kernel<<<Nn / 64, 128>>>(W1, b1, HID, 1);       // 11

    gather_kernel<<<Nn * 32 / 256, 256>>>();                  // 12
    gemm_tanh_kernel<<<Nn / 64, 128>>>(W2, b2, 2 * HID, 0);   // 13

    head_kernel<<<Bb, 256>>>(Wc1, bc1, Wc2, bc2, g1, be1, g2, be2,
                             Wl1, bl1, Wl2, bl2, rm1, rv1, rm2, rv2, out);  // 14
}